// round 3
// baseline (speedup 1.0000x reference)
#include <cuda_runtime.h>
#include <cuda_bf16.h>

#define S 128
#define NROWS 4096
#define RPB 4                   // rows per block; 2 warps per row -> 256 threads
#define NBLK (NROWS / RPB)      // 1024 blocks

__device__ float4 g_part[NBLK];
__device__ unsigned int g_ticket;   // zero at load; reset by last block each run

__global__ void __launch_bounds__(256) loss3_fused(const float* __restrict__ outp,
                                                   const float* __restrict__ trut,
                                                   float* __restrict__ out) {
    __shared__ float so2[RPB][2 * S];   // output row, duplicated (wrap-free)
    __shared__ float st[RPB][S];        // truth row
    __shared__ float xacc[RPB][S];      // half-1 partial correlations
    __shared__ float xred[RPB][8];      // [half*4 + {ms,mo,mt,gg}]
    __shared__ float xbs[RPB][4];       // {bestShift, scale, msTotal}
    __shared__ unsigned int sLast;

    const int tid = threadIdx.x;
    const int w  = tid >> 6;          // row within block
    const int h  = (tid >> 5) & 1;    // warp-half of the row
    const int l  = tid & 31;          // lane
    const int gl = tid & 63;          // thread within row-group
    const int row = blockIdx.x * RPB + w;

    // ---- load half-row (coalesced float2), mirror into smem ----
    const int eb = 64 * h + 2 * l;
    float2 o2 = *(const float2*)(outp + row * S + eb);
    float2 t2 = *(const float2*)(trut + row * S + eb);
    *(float2*)&so2[w][eb]     = o2;
    *(float2*)&so2[w][eb + S] = o2;
    *(float2*)&st[w][eb]      = t2;

    // ---- half-row MSE, max(output), max(truth) via warp shuffles ----
    float dx = o2.x - t2.x, dy = o2.y - t2.y;
    float ms = dx * dx + dy * dy;
    float mo = fmaxf(o2.x, o2.y);
    float mt = fmaxf(t2.x, t2.y);
#pragma unroll
    for (int s = 16; s > 0; s >>= 1) {
        ms += __shfl_xor_sync(0xffffffffu, ms, s);
        mo = fmaxf(mo, __shfl_xor_sync(0xffffffffu, mo, s));
        mt = fmaxf(mt, __shfl_xor_sync(0xffffffffu, mt, s));
    }
    if (l == 0) {
        xred[w][h * 4 + 0] = ms;
        xred[w][h * 4 + 1] = mo;
        xred[w][h * 4 + 2] = mt;
    }
    __syncthreads();

    // ---- circular correlation, j-range split across warp pair ----
    // acc[k] = sum_{j in half} o[(j-(4l+k))&127] * t[j];  o[(j-s)&127]=so2[j-s+S]
    const float* ob = &so2[w][S - 4 * l - 4];
    const float* tb = &st[w][0];
    float acc0 = 0.f, acc1 = 0.f, acc2 = 0.f, acc3 = 0.f;
    float4 W0 = *(const float4*)(ob + 64 * h);
#pragma unroll
    for (int J = 64 * h; J < 64 * h + 64; J += 4) {
        float4 W1 = *(const float4*)(ob + J + 4);
        float4 tt = *(const float4*)(tb + J);   // uniform -> smem broadcast
        acc0 = fmaf(W1.x, tt.x, acc0);
        acc1 = fmaf(W0.w, tt.x, acc1);
        acc2 = fmaf(W0.z, tt.x, acc2);
        acc3 = fmaf(W0.y, tt.x, acc3);
        acc0 = fmaf(W1.y, tt.y, acc0);
        acc1 = fmaf(W1.x, tt.y, acc1);
        acc2 = fmaf(W0.w, tt.y, acc2);
        acc3 = fmaf(W0.z, tt.y, acc3);
        acc0 = fmaf(W1.z, tt.z, acc0);
        acc1 = fmaf(W1.y, tt.z, acc1);
        acc2 = fmaf(W1.x, tt.z, acc2);
        acc3 = fmaf(W0.w, tt.z, acc3);
        acc0 = fmaf(W1.w, tt.w, acc0);
        acc1 = fmaf(W1.z, tt.w, acc1);
        acc2 = fmaf(W1.y, tt.w, acc2);
        acc3 = fmaf(W1.x, tt.w, acc3);
        W0 = W1;
    }
    if (h == 1) *(float4*)&xacc[w][4 * l] = make_float4(acc0, acc1, acc2, acc3);
    __syncthreads();

    // ---- warp-half 0 combines partials; argmax corr (tie -> smaller shift) ----
    if (h == 0) {
        float4 pb = *(const float4*)&xacc[w][4 * l];
        acc0 += pb.x; acc1 += pb.y; acc2 += pb.z; acc3 += pb.w;
        float bc = acc0; int bs = 4 * l;
        if (acc1 > bc) { bc = acc1; bs = 4 * l + 1; }
        if (acc2 > bc) { bc = acc2; bs = 4 * l + 2; }
        if (acc3 > bc) { bc = acc3; bs = 4 * l + 3; }
#pragma unroll
        for (int s = 16; s > 0; s >>= 1) {
            float oc = __shfl_xor_sync(0xffffffffu, bc, s);
            int   os = __shfl_xor_sync(0xffffffffu, bs, s);
            if (oc > bc || (oc == bc && os < bs)) { bc = oc; bs = os; }
        }
        if (l == 0) {
            float moT = fmaxf(xred[w][1], xred[w][5]);
            float mtT = fmaxf(xred[w][2], xred[w][6]);
            xbs[w][0] = (float)bs;
            xbs[w][1] = mtT / moT;           // max(rolled)==max(output)
            xbs[w][2] = xred[w][0] + xred[w][4];
        }
    }
    __syncthreads();
    const int   b     = (int)xbs[w][0];
    const float scale = xbs[w][1];

    // ---- detail loss: g = cgrad(rolled*scale - truth); 2 elems/thread ----
    float gg;
    {
        const int i = 2 * gl;
        float dm = so2[w][(i - 1 - b) & 127] * scale - st[w][(i - 1) & 127];
        float d0 = so2[w][(i     - b) & 127] * scale - st[w][i];
        float d1 = so2[w][(i + 1 - b) & 127] * scale - st[w][(i + 1) & 127];
        float d2 = so2[w][(i + 2 - b) & 127] * scale - st[w][(i + 2) & 127];
        float g0 = d0 - 0.5f * (dm + d1);
        float g1 = d1 - 0.5f * (d0 + d2);
        gg = g0 * g0 + g1 * g1;
    }
#pragma unroll
    for (int s = 16; s > 0; s >>= 1) gg += __shfl_xor_sync(0xffffffffu, gg, s);
    if (l == 0) xred[w][h * 4 + 3] = gg;
    __syncthreads();

    // ---- per-block partial, fixed order ----
    if (tid == 0) {
        float4 r = make_float4(0.f, 0.f, 0.f, 0.f);
#pragma unroll
        for (int k = 0; k < RPB; k++) {
            r.x += xbs[k][0];
            r.y += fabsf(xbs[k][1] - 1.0f);
            r.z += sqrtf(xred[k][3] + xred[k][7]);
            r.w += xbs[k][2];
        }
        g_part[blockIdx.x] = r;
        __threadfence();
        unsigned int old = atomicAdd(&g_ticket, 1u);
        sLast = (old == NBLK - 1) ? 1u : 0u;
    }
    __syncthreads();

    // ---- last block finalizes (deterministic fixed-order reduction) ----
    if (sLast) {
        float a = 0.f, bb = 0.f, c = 0.f, dd = 0.f;
#pragma unroll
        for (int i = tid; i < NBLK; i += 256) {
            float4 q = g_part[i];
            a += q.x; bb += q.y; c += q.z; dd += q.w;
        }
        float4* fr = (float4*)&so2[0][0];   // 256*16B == sizeof(so2), reuse
        fr[tid] = make_float4(a, bb, c, dd);
        __syncthreads();
#pragma unroll
        for (int stp = 128; stp > 0; stp >>= 1) {
            if (tid < stp) {
                float4 x = fr[tid], y = fr[tid + stp];
                fr[tid] = make_float4(x.x + y.x, x.y + y.y, x.z + y.z, x.w + y.w);
            }
            __syncthreads();
        }
        if (tid == 0) {
            float4 r = fr[0];
            out[0] = 50.0f * r.x + 100.0f * r.y + 0.1f * r.z + sqrtf(r.w);
            g_ticket = 0u;   // reset for graph replay
        }
    }
}

extern "C" void kernel_launch(void* const* d_in, const int* in_sizes, int n_in,
                              void* d_out, int out_size) {
    (void)n_in; (void)out_size; (void)in_sizes;
    const float* outp = (const float*)d_in[0];
    const float* trut = (const float*)d_in[1];
    float* res = (float*)d_out;
    loss3_fused<<<NBLK, 256>>>(outp, trut, res);
}

// round 4
// speedup vs baseline: 1.0599x; 1.0599x over previous
#include <cuda_runtime.h>
#include <cuda_bf16.h>

#define S 128
#define NROWS 4096
#define RPB 4                 // rows per block (one warp per row)
#define NBLK (NROWS / RPB)    // 1024 blocks

__device__ float4 g_part[NBLK];
__device__ unsigned int g_ticket;   // zero at load; reset by last block each run

__global__ void __launch_bounds__(128, 7) loss3_fused(const float* __restrict__ outp,
                                                      const float* __restrict__ trut,
                                                      float* __restrict__ out) {
    __shared__ float so2[RPB][2 * S];   // output row, duplicated (wrap-free)
    __shared__ float st[RPB][S];        // truth row
    __shared__ float4 wres[RPB];
    __shared__ unsigned int sLast;

    const int tid = threadIdx.x;
    const int w = tid >> 5;     // warp = row within block
    const int l = tid & 31;     // lane
    const int row = blockIdx.x * RPB + w;

    // ---- load row (coalesced float4), mirror into smem ----
    float4 o4 = *(const float4*)(outp + row * S + 4 * l);
    float4 t4 = *(const float4*)(trut + row * S + 4 * l);
    *(float4*)&so2[w][4 * l]     = o4;
    *(float4*)&so2[w][S + 4 * l] = o4;
    *(float4*)&st[w][4 * l]      = t4;
    __syncwarp();

    // ---- row MSE (direct), max(output), max(truth): warp shuffles ----
    float d0 = o4.x - t4.x, d1 = o4.y - t4.y, d2 = o4.z - t4.z, d3 = o4.w - t4.w;
    float ms = d0 * d0 + d1 * d1 + d2 * d2 + d3 * d3;
    float mo = fmaxf(fmaxf(o4.x, o4.y), fmaxf(o4.z, o4.w));
    float mt = fmaxf(fmaxf(t4.x, t4.y), fmaxf(t4.z, t4.w));
#pragma unroll
    for (int s = 16; s > 0; s >>= 1) {
        ms += __shfl_xor_sync(0xffffffffu, ms, s);
        mo = fmaxf(mo, __shfl_xor_sync(0xffffffffu, mo, s));
        mt = fmaxf(mt, __shfl_xor_sync(0xffffffffu, mt, s));
    }

    // ---- circular correlation: acc[k] = sum_j o[(j-(4l+k))&127] * t[j] ----
    // o[(j-s)&127] = so2[j - s + S].  base = S - 4l - 4 (16B aligned).
    // 8 accumulators (even/odd J-step banks) to break FFMA chains; full
    // unroll + 72-reg budget lets ptxas pipeline the LDS.128s ahead.
    const float* ob = &so2[w][S - 4 * l - 4];
    const float* tb = &st[w][0];
    float a0 = 0.f, a1 = 0.f, a2 = 0.f, a3 = 0.f;
    float b0 = 0.f, b1 = 0.f, b2 = 0.f, b3 = 0.f;
    float4 W0 = *(const float4*)(ob);            // W[0..3]
#pragma unroll
    for (int J = 0; J < S; J += 8) {
        float4 W1 = *(const float4*)(ob + J + 4);
        float4 T0 = *(const float4*)(tb + J);        // uniform -> broadcast
        a0 = fmaf(W1.x, T0.x, a0);
        a1 = fmaf(W0.w, T0.x, a1);
        a2 = fmaf(W0.z, T0.x, a2);
        a3 = fmaf(W0.y, T0.x, a3);
        a0 = fmaf(W1.y, T0.y, a0);
        a1 = fmaf(W1.x, T0.y, a1);
        a2 = fmaf(W0.w, T0.y, a2);
        a3 = fmaf(W0.z, T0.y, a3);
        a0 = fmaf(W1.z, T0.z, a0);
        a1 = fmaf(W1.y, T0.z, a1);
        a2 = fmaf(W1.x, T0.z, a2);
        a3 = fmaf(W0.w, T0.z, a3);
        a0 = fmaf(W1.w, T0.w, a0);
        a1 = fmaf(W1.z, T0.w, a1);
        a2 = fmaf(W1.y, T0.w, a2);
        a3 = fmaf(W1.x, T0.w, a3);
        float4 W2 = *(const float4*)(ob + J + 8);
        float4 T1 = *(const float4*)(tb + J + 4);
        b0 = fmaf(W2.x, T1.x, b0);
        b1 = fmaf(W1.w, T1.x, b1);
        b2 = fmaf(W1.z, T1.x, b2);
        b3 = fmaf(W1.y, T1.x, b3);
        b0 = fmaf(W2.y, T1.y, b0);
        b1 = fmaf(W2.x, T1.y, b1);
        b2 = fmaf(W1.w, T1.y, b2);
        b3 = fmaf(W1.z, T1.y, b3);
        b0 = fmaf(W2.z, T1.z, b0);
        b1 = fmaf(W2.y, T1.z, b1);
        b2 = fmaf(W2.x, T1.z, b2);
        b3 = fmaf(W1.w, T1.z, b3);
        b0 = fmaf(W2.w, T1.w, b0);
        b1 = fmaf(W2.z, T1.w, b1);
        b2 = fmaf(W2.y, T1.w, b2);
        b3 = fmaf(W2.x, T1.w, b3);
        W0 = W2;
    }
    float acc0 = a0 + b0, acc1 = a1 + b1, acc2 = a2 + b2, acc3 = a3 + b3;

    // ---- argmax corr == argmin shiftDiff; tie-break -> smaller shift ----
    float bc = acc0; int bs = 4 * l;
    if (acc1 > bc) { bc = acc1; bs = 4 * l + 1; }
    if (acc2 > bc) { bc = acc2; bs = 4 * l + 2; }
    if (acc3 > bc) { bc = acc3; bs = 4 * l + 3; }
#pragma unroll
    for (int s = 16; s > 0; s >>= 1) {
        float oc = __shfl_xor_sync(0xffffffffu, bc, s);
        int   os = __shfl_xor_sync(0xffffffffu, bs, s);
        if (oc > bc || (oc == bc && os < bs)) { bc = oc; bs = os; }
    }
    const int b = bs;
    const float scale = mt / mo;   // max(rolled) == max(output): roll is a permutation

    // ---- detail loss: g = cgrad(rolled*scale - truth), cgrad linear ----
    float gg = 0.f;
#pragma unroll
    for (int m = 0; m < 4; m++) {
        int i = 4 * l + m;
        float dm1 = so2[w][(i - 1 - b) & 127] * scale - st[w][(i - 1) & 127];
        float dc  = so2[w][(i     - b) & 127] * scale - st[w][i];
        float dp1 = so2[w][(i + 1 - b) & 127] * scale - st[w][(i + 1) & 127];
        float g = dc - 0.5f * (dm1 + dp1);
        gg = fmaf(g, g, gg);
    }
#pragma unroll
    for (int s = 16; s > 0; s >>= 1) gg += __shfl_xor_sync(0xffffffffu, gg, s);

    // ---- per-block partial (fixed order: warp 0..3) ----
    if (l == 0) wres[w] = make_float4((float)b, fabsf(scale - 1.0f), sqrtf(gg), ms);
    __syncthreads();
    if (tid == 0) {
        float4 r = wres[0];
#pragma unroll
        for (int k = 1; k < RPB; k++) {
            float4 q = wres[k];
            r.x += q.x; r.y += q.y; r.z += q.z; r.w += q.w;
        }
        g_part[blockIdx.x] = r;
        __threadfence();
        unsigned int old = atomicAdd(&g_ticket, 1u);
        sLast = (old == NBLK - 1) ? 1u : 0u;
    }
    __syncthreads();

    // ---- last block finalizes (deterministic fixed-order reduction) ----
    if (sLast) {
        float a = 0.f, bb = 0.f, c = 0.f, dd = 0.f;
#pragma unroll
        for (int i = tid; i < NBLK; i += 128) {
            float4 q = g_part[i];
            a += q.x; bb += q.y; c += q.z; dd += q.w;
        }
        float4* fr = (float4*)&so2[0][0];   // reuse smem
        fr[tid] = make_float4(a, bb, c, dd);
        __syncthreads();
#pragma unroll
        for (int stp = 64; stp > 0; stp >>= 1) {
            if (tid < stp) {
                float4 x = fr[tid], y = fr[tid + stp];
                fr[tid] = make_float4(x.x + y.x, x.y + y.y, x.z + y.z, x.w + y.w);
            }
            __syncthreads();
        }
        if (tid == 0) {
            float4 r = fr[0];
            out[0] = 50.0f * r.x + 100.0f * r.y + 0.1f * r.z + sqrtf(r.w);
            g_ticket = 0u;   // reset for next graph replay
        }
    }
}

extern "C" void kernel_launch(void* const* d_in, const int* in_sizes, int n_in,
                              void* d_out, int out_size) {
    (void)n_in; (void)out_size; (void)in_sizes;
    const float* outp = (const float*)d_in[0];
    const float* trut = (const float*)d_in[1];
    float* res = (float*)d_out;
    loss3_fused<<<NBLK, 128>>>(outp, trut, res);
}